// round 4
// baseline (speedup 1.0000x reference)
#include <cuda_runtime.h>
#include <math.h>

#define BATCH   64
#define DIN     1024
#define DOUT    1024
#define ISPLITS 64
#define ICHUNK  (DIN / ISPLITS)     // 16
#define BTILE   8
#define BTILES  (BATCH / BTILE)     // 8
#define THREADS 256                 // 256 threads * 4 floats = 1024 = DOUT

// Scratch (static __device__ globals — allocation-free per harness rules)
__device__ float g_sigma[DIN * DOUT];                    // 4 MB: softplus(ro)
__device__ float g_part[ISPLITS * BATCH * DOUT];         // 16 MB: i-split partials

__device__ __forceinline__ float softplus_f(float v) {
    // numerically stable: max(v,0) + log1p(exp(-|v|))
    return fmaxf(v, 0.0f) + log1pf(expf(-fabsf(v)));
}

// ---------------------------------------------------------------------------
// Kernel 1: sigma = softplus(ro), vectorized float4. 1M elems.
// ---------------------------------------------------------------------------
__global__ void sigma_kernel(const float* __restrict__ ro) {
    int idx = blockIdx.x * blockDim.x + threadIdx.x;   // float4 index
    const float4* r4 = reinterpret_cast<const float4*>(ro);
    float4*       s4 = reinterpret_cast<float4*>(g_sigma);
    float4 r = r4[idx];
    float4 s;
    s.x = softplus_f(r.x);
    s.y = softplus_f(r.y);
    s.z = softplus_f(r.z);
    s.w = softplus_f(r.w);
    s4[idx] = s;
}

// ---------------------------------------------------------------------------
// Kernel 2: main streaming reduction.
// grid = (ISPLITS, BTILES). Each CTA: 8 batches x 16 i x all 1024 o.
// Each thread: 4 consecutive o (float4), 8 batches -> 32 accumulators.
// sigma/mu loaded once per (i, o4) and applied to 8 batches (8x LTS saving).
// ---------------------------------------------------------------------------
__global__ __launch_bounds__(THREADS) void main_kernel(
    const float* __restrict__ x,
    const float* __restrict__ mu,
    const float* __restrict__ eps)
{
    const int ic = blockIdx.x;           // i-chunk: 0..63
    const int bt = blockIdx.y;           // b-tile:  0..7
    const int i0 = ic * ICHUNK;
    const int b0 = bt * BTILE;
    const int o4 = threadIdx.x;          // float4 index along o

    __shared__ float sx[BTILE][ICHUNK];  // 8 x 16 x values
    {
        int t = threadIdx.x;
        if (t < BTILE * ICHUNK) {        // first 128 threads
            int bb = t / ICHUNK;
            int ii = t % ICHUNK;
            sx[bb][ii] = x[(b0 + bb) * DIN + i0 + ii];
        }
    }
    __syncthreads();

    float4 acc[BTILE];
#pragma unroll
    for (int bb = 0; bb < BTILE; bb++) acc[bb] = make_float4(0.f, 0.f, 0.f, 0.f);

    const float4* sig4 = reinterpret_cast<const float4*>(g_sigma);
    const float4* mu4  = reinterpret_cast<const float4*>(mu);
    const float4* eps4 = reinterpret_cast<const float4*>(eps);

#pragma unroll 2
    for (int ii = 0; ii < ICHUNK; ii++) {
        const int i = i0 + ii;
        const int row = i * (DOUT / 4) + o4;           // < 256K, 32-bit safe
        const float4 sg = sig4[row];
        const float4 m  = mu4[row];
#pragma unroll
        for (int bb = 0; bb < BTILE; bb++) {
            const float xv = sx[bb][ii];
            // eps float4 index: ((b*DIN + i) * DOUT + o) / 4  <= 16.7M, 32-bit safe
            const float4 e = eps4[((b0 + bb) * DIN + i) * (DOUT / 4) + o4];
            acc[bb].x = fmaf(xv, fmaf(e.x, sg.x, m.x), acc[bb].x);
            acc[bb].y = fmaf(xv, fmaf(e.y, sg.y, m.y), acc[bb].y);
            acc[bb].z = fmaf(xv, fmaf(e.z, sg.z, m.z), acc[bb].z);
            acc[bb].w = fmaf(xv, fmaf(e.w, sg.w, m.w), acc[bb].w);
        }
    }

    float4* p4 = reinterpret_cast<float4*>(g_part);
#pragma unroll
    for (int bb = 0; bb < BTILE; bb++) {
        p4[(ic * BATCH + b0 + bb) * (DOUT / 4) + o4] = acc[bb];
    }
}

// ---------------------------------------------------------------------------
// Kernel 3: deterministic reduction over ISPLITS partials + bias.
// out[b,o] = sum_s part[s][b][o] + eps_bias[b,o]*softplus(ro_bias[o]) + mu_bias[o]
// ---------------------------------------------------------------------------
__global__ void reduce_kernel(
    const float* __restrict__ mu_bias,
    const float* __restrict__ ro_bias,
    const float* __restrict__ eps_bias,
    float* __restrict__ out)
{
    const int gid = blockIdx.x * blockDim.x + threadIdx.x;  // b*DOUT + o
    const int o = gid & (DOUT - 1);

    float sum = 0.0f;
#pragma unroll 8
    for (int s = 0; s < ISPLITS; s++) {
        sum += g_part[s * (BATCH * DOUT) + gid];
    }
    const float spb = softplus_f(ro_bias[o]);
    out[gid] = sum + fmaf(eps_bias[gid], spb, mu_bias[o]);
}

// ---------------------------------------------------------------------------
// Launch. Inputs (metadata order): x, mu, ro, mu_bias, ro_bias, eps, eps_bias
// ---------------------------------------------------------------------------
extern "C" void kernel_launch(void* const* d_in, const int* in_sizes, int n_in,
                              void* d_out, int out_size) {
    const float* x        = (const float*)d_in[0];
    const float* mu       = (const float*)d_in[1];
    const float* ro       = (const float*)d_in[2];
    const float* mu_bias  = (const float*)d_in[3];
    const float* ro_bias  = (const float*)d_in[4];
    const float* eps      = (const float*)d_in[5];
    const float* eps_bias = (const float*)d_in[6];
    float* out = (float*)d_out;

    // K1: softplus(ro) -> g_sigma   (1M elems / 4 per thread / 256 per block)
    sigma_kernel<<<(DIN * DOUT / 4) / 256, 256>>>(ro);

    // K2: streaming batched matvec partials
    dim3 grid(ISPLITS, BTILES);
    main_kernel<<<grid, THREADS>>>(x, mu, eps);

    // K3: reduce partials + bias
    reduce_kernel<<<(BATCH * DOUT) / 256, 256>>>(mu_bias, ro_bias, eps_bias, out);
}

// round 7
// speedup vs baseline: 1.2775x; 1.2775x over previous
#include <cuda_runtime.h>
#include <math.h>

#define BATCH   64
#define DIN     1024
#define DOUT    1024
#define ISPLITS 32
#define ICHUNK  (DIN / ISPLITS)     // 32
#define BTILE   8
#define BTILES  (BATCH / BTILE)     // 8
#define THREADS 256                 // 256 threads * float4 = 1024 = DOUT

// Scratch (static __device__ global — allocation-free per harness rules)
__device__ float g_part[ISPLITS * BATCH * DOUT];   // 8 MB: i-split partials

// Fast softplus: max(v,0) + log1p(exp(-|v|)) with MUFU intrinsics.
// |rel err| << 1e-3 tolerance (harness passes at 6e-7 with accurate version).
__device__ __forceinline__ float softplus_fast(float v) {
    float e = __expf(-fabsf(v));
    return fmaxf(v, 0.0f) + __logf(1.0f + e);
}

// ---------------------------------------------------------------------------
// Kernel 1 (main): streaming batched matvec partials with inline softplus.
// grid = (ISPLITS, BTILES) = (32, 8) = 256 CTAs.
// Each CTA: 8 batches x 32 i x all 1024 o. Each thread: 4 consecutive o.
// ro/mu loaded once per (i, o4), softplus computed inline, applied to 8
// batches (8x L2 reuse; ro+mu stay L2-resident because eps uses evict-first).
// ---------------------------------------------------------------------------
__global__ __launch_bounds__(THREADS) void main_kernel(
    const float* __restrict__ x,
    const float* __restrict__ mu,
    const float* __restrict__ ro,
    const float* __restrict__ eps)
{
    const int ic = blockIdx.x;           // i-chunk: 0..31
    const int bt = blockIdx.y;           // b-tile:  0..7
    const int i0 = ic * ICHUNK;
    const int b0 = bt * BTILE;
    const int o4 = threadIdx.x;          // float4 index along o

    __shared__ float sx[BTILE][ICHUNK];  // 8 x 32 = 256 values
    {
        const int t  = threadIdx.x;      // exactly 256 threads
        const int bb = t / ICHUNK;
        const int ii = t % ICHUNK;
        sx[bb][ii] = x[(b0 + bb) * DIN + i0 + ii];
    }
    __syncthreads();

    float4 acc[BTILE];
#pragma unroll
    for (int bb = 0; bb < BTILE; bb++) acc[bb] = make_float4(0.f, 0.f, 0.f, 0.f);

    const float4* ro4  = reinterpret_cast<const float4*>(ro);
    const float4* mu4  = reinterpret_cast<const float4*>(mu);
    const float4* eps4 = reinterpret_cast<const float4*>(eps);

    int row   = i0 * (DOUT / 4) + o4;                    // ro/mu float4 index
    int ebase = (b0 * DIN + i0) * (DOUT / 4) + o4;       // eps float4 index (<= 16.7M)

#pragma unroll 4
    for (int ii = 0; ii < ICHUNK; ii++) {
        const float4 r = ro4[row];
        const float4 m = mu4[row];
        float4 sg;
        sg.x = softplus_fast(r.x);
        sg.y = softplus_fast(r.y);
        sg.z = softplus_fast(r.z);
        sg.w = softplus_fast(r.w);
#pragma unroll
        for (int bb = 0; bb < BTILE; bb++) {
            const float  xv = sx[bb][ii];
            // evict-first: eps is touched exactly once chip-wide
            const float4 e = __ldcs(&eps4[ebase + bb * (DIN * (DOUT / 4))]);
            acc[bb].x = fmaf(xv, fmaf(e.x, sg.x, m.x), acc[bb].x);
            acc[bb].y = fmaf(xv, fmaf(e.y, sg.y, m.y), acc[bb].y);
            acc[bb].z = fmaf(xv, fmaf(e.z, sg.z, m.z), acc[bb].z);
            acc[bb].w = fmaf(xv, fmaf(e.w, sg.w, m.w), acc[bb].w);
        }
        row   += DOUT / 4;
        ebase += DOUT / 4;
    }

    float4* p4 = reinterpret_cast<float4*>(g_part);
#pragma unroll
    for (int bb = 0; bb < BTILE; bb++) {
        __stcs(&p4[(ic * BATCH + b0 + bb) * (DOUT / 4) + o4], acc[bb]);
    }
}

// ---------------------------------------------------------------------------
// Kernel 2: deterministic reduction over ISPLITS partials + bias.
// Vectorized float4; 16384 threads = 128 blocks x 128 threads.
// out[b,o] = sum_s part[s][b][o] + eps_bias[b,o]*softplus(ro_bias[o]) + mu_bias[o]
// ---------------------------------------------------------------------------
__global__ void reduce_kernel(
    const float* __restrict__ mu_bias,
    const float* __restrict__ ro_bias,
    const float* __restrict__ eps_bias,
    float* __restrict__ out)
{
    const int g4 = blockIdx.x * blockDim.x + threadIdx.x;   // float4 idx over B*DOUT/4
    const int o4 = g4 & (DOUT / 4 - 1);                     // float4 idx along o

    const float4* p4 = reinterpret_cast<const float4*>(g_part);
    float4 sum = make_float4(0.f, 0.f, 0.f, 0.f);
#pragma unroll
    for (int s = 0; s < ISPLITS; s++) {
        const float4 p = __ldcs(&p4[s * (BATCH * DOUT / 4) + g4]);
        sum.x += p.x; sum.y += p.y; sum.z += p.z; sum.w += p.w;
    }

    const float4 rb = reinterpret_cast<const float4*>(ro_bias)[o4];
    const float4 mb = reinterpret_cast<const float4*>(mu_bias)[o4];
    const float4 eb = reinterpret_cast<const float4*>(eps_bias)[g4];

    float4 r;
    r.x = sum.x + fmaf(eb.x, softplus_fast(rb.x), mb.x);
    r.y = sum.y + fmaf(eb.y, softplus_fast(rb.y), mb.y);
    r.z = sum.z + fmaf(eb.z, softplus_fast(rb.z), mb.z);
    r.w = sum.w + fmaf(eb.w, softplus_fast(rb.w), mb.w);
    reinterpret_cast<float4*>(out)[g4] = r;
}

// ---------------------------------------------------------------------------
// Launch. Inputs (metadata order): x, mu, ro, mu_bias, ro_bias, eps, eps_bias
// ---------------------------------------------------------------------------
extern "C" void kernel_launch(void* const* d_in, const int* in_sizes, int n_in,
                              void* d_out, int out_size) {
    const float* x        = (const float*)d_in[0];
    const float* mu       = (const float*)d_in[1];
    const float* ro       = (const float*)d_in[2];
    const float* mu_bias  = (const float*)d_in[3];
    const float* ro_bias  = (const float*)d_in[4];
    const float* eps      = (const float*)d_in[5];
    const float* eps_bias = (const float*)d_in[6];
    float* out = (float*)d_out;

    dim3 grid(ISPLITS, BTILES);
    main_kernel<<<grid, THREADS>>>(x, mu, ro, eps);

    reduce_kernel<<<(BATCH * DOUT / 4) / 128, 128>>>(mu_bias, ro_bias, eps_bias, out);
}

// round 8
// speedup vs baseline: 1.3265x; 1.0384x over previous
#include <cuda_runtime.h>
#include <math.h>

#define BATCH    64
#define DIN      1024
#define DOUT     1024
#define ISPLITS  37                  // grid = 37*8 = 296 = 2 CTAs per SM (148 SMs)
#define CHUNK_HI 28                  // first 25 chunks: 28 rows
#define CHUNK_LO 27                  // last 12 chunks: 27 rows (25*28+12*27 = 1024)
#define N_HI     25
#define BTILE    8
#define BTILES   (BATCH / BTILE)     // 8
#define THREADS  256                 // 256 threads * float4 = 1024 = DOUT

// Scratch (static __device__ global — allocation-free per harness rules)
__device__ float g_part[ISPLITS * BATCH * DOUT];   // 9.7 MB: i-split partials

// Fast softplus: max(v,0) + log1p(exp(-|v|)) with MUFU intrinsics.
__device__ __forceinline__ float softplus_fast(float v) {
    float e = __expf(-fabsf(v));
    return fmaxf(v, 0.0f) + __logf(1.0f + e);
}

// ---------------------------------------------------------------------------
// Kernel 1 (main): streaming batched matvec partials with inline softplus.
// grid = (ISPLITS, BTILES) = (37, 8) = 296 CTAs -> exactly 2 per SM, balanced.
// Each CTA: 8 batches x {27|28} i-rows x all 1024 o. Thread: 4 consecutive o.
// ro/mu loaded once per (i,o4), softplus inline, applied to 8 batches.
// eps / partials use evict-first so ro+mu stay L2-resident across b-tiles.
// ---------------------------------------------------------------------------
__global__ __launch_bounds__(THREADS) void main_kernel(
    const float* __restrict__ x,
    const float* __restrict__ mu,
    const float* __restrict__ ro,
    const float* __restrict__ eps)
{
    const int ic  = blockIdx.x;          // i-chunk: 0..36
    const int bt  = blockIdx.y;          // b-tile:  0..7
    const int len = (ic < N_HI) ? CHUNK_HI : CHUNK_LO;
    const int i0  = (ic < N_HI) ? ic * CHUNK_HI
                                : N_HI * CHUNK_HI + (ic - N_HI) * CHUNK_LO;
    const int b0  = bt * BTILE;
    const int o4  = threadIdx.x;         // float4 index along o

    __shared__ float sx[BTILE][CHUNK_HI];   // 8 x 28 max
    {
        const int t = threadIdx.x;
        if (t < BTILE * len) {              // <= 224 < 256
            const int bb = t / len;
            const int ii = t % len;
            sx[bb][ii] = x[(b0 + bb) * DIN + i0 + ii];
        }
    }
    __syncthreads();

    float4 acc[BTILE];
#pragma unroll
    for (int bb = 0; bb < BTILE; bb++) acc[bb] = make_float4(0.f, 0.f, 0.f, 0.f);

    const float4* ro4  = reinterpret_cast<const float4*>(ro);
    const float4* mu4  = reinterpret_cast<const float4*>(mu);
    const float4* eps4 = reinterpret_cast<const float4*>(eps);

    int row   = i0 * (DOUT / 4) + o4;               // ro/mu float4 index
    int ebase = (b0 * DIN + i0) * (DOUT / 4) + o4;  // eps float4 index (<=16.7M)

#pragma unroll 4
    for (int ii = 0; ii < len; ii++) {
        const float4 r = ro4[row];
        const float4 m = mu4[row];
        float4 sg;
        sg.x = softplus_fast(r.x);
        sg.y = softplus_fast(r.y);
        sg.z = softplus_fast(r.z);
        sg.w = softplus_fast(r.w);
#pragma unroll
        for (int bb = 0; bb < BTILE; bb++) {
            const float  xv = sx[bb][ii];
            const float4 e  = __ldcs(&eps4[ebase + bb * (DIN * (DOUT / 4))]);
            acc[bb].x = fmaf(xv, fmaf(e.x, sg.x, m.x), acc[bb].x);
            acc[bb].y = fmaf(xv, fmaf(e.y, sg.y, m.y), acc[bb].y);
            acc[bb].z = fmaf(xv, fmaf(e.z, sg.z, m.z), acc[bb].z);
            acc[bb].w = fmaf(xv, fmaf(e.w, sg.w, m.w), acc[bb].w);
        }
        row   += DOUT / 4;
        ebase += DOUT / 4;
    }

    float4* p4 = reinterpret_cast<float4*>(g_part);
#pragma unroll
    for (int bb = 0; bb < BTILE; bb++) {
        __stcs(&p4[(ic * BATCH + b0 + bb) * (DOUT / 4) + o4], acc[bb]);
    }
}

// ---------------------------------------------------------------------------
// Kernel 2: deterministic reduction over ISPLITS partials + bias.
// 256 blocks x 256 threads = 64K threads (vs 16K before: occupancy fix).
// Block = 4 split-groups x 64 output-float4s. Each thread sums ~ISPLITS/4
// splits for one output float4; 4-way smem reduce, then bias + store.
// ---------------------------------------------------------------------------
#define RED_GROUPS 4
#define RED_OUTS   64                // float4 outputs per block
#define SPG        10                // splits per group (last group gets 7)

__global__ __launch_bounds__(RED_GROUPS * RED_OUTS) void reduce_kernel(
    const float* __restrict__ mu_bias,
    const float* __restrict__ ro_bias,
    const float* __restrict__ eps_bias,
    float* __restrict__ out)
{
    const int t  = threadIdx.x & (RED_OUTS - 1);    // output lane within block
    const int g  = threadIdx.x / RED_OUTS;          // split group 0..3
    const int g4 = blockIdx.x * RED_OUTS + t;       // float4 idx over B*DOUT/4

    const float4* p4 = reinterpret_cast<const float4*>(g_part);

    const int s_lo = g * SPG;
    const int s_hi = min(ISPLITS, s_lo + SPG);
    float4 sum = make_float4(0.f, 0.f, 0.f, 0.f);
    for (int s = s_lo; s < s_hi; s++) {
        const float4 p = __ldcs(&p4[s * (BATCH * DOUT / 4) + g4]);
        sum.x += p.x; sum.y += p.y; sum.z += p.z; sum.w += p.w;
    }

    __shared__ float4 red[RED_GROUPS][RED_OUTS];
    red[g][t] = sum;
    __syncthreads();

    if (g == 0) {
#pragma unroll
        for (int k = 1; k < RED_GROUPS; k++) {
            const float4 p = red[k][t];
            sum.x += p.x; sum.y += p.y; sum.z += p.z; sum.w += p.w;
        }
        const int o4 = g4 & (DOUT / 4 - 1);
        const float4 rb = reinterpret_cast<const float4*>(ro_bias)[o4];
        const float4 mb = reinterpret_cast<const float4*>(mu_bias)[o4];
        const float4 eb = reinterpret_cast<const float4*>(eps_bias)[g4];

        float4 r;
        r.x = sum.x + fmaf(eb.x, softplus_fast(rb.x), mb.x);
        r.y = sum.y + fmaf(eb.y, softplus_fast(rb.y), mb.y);
        r.z = sum.z + fmaf(eb.z, softplus_fast(rb.z), mb.z);
        r.w = sum.w + fmaf(eb.w, softplus_fast(rb.w), mb.w);
        reinterpret_cast<float4*>(out)[g4] = r;
    }
}

// ---------------------------------------------------------------------------
// Launch. Inputs (metadata order): x, mu, ro, mu_bias, ro_bias, eps, eps_bias
// ---------------------------------------------------------------------------
extern "C" void kernel_launch(void* const* d_in, const int* in_sizes, int n_in,
                              void* d_out, int out_size) {
    const float* x        = (const float*)d_in[0];
    const float* mu       = (const float*)d_in[1];
    const float* ro       = (const float*)d_in[2];
    const float* mu_bias  = (const float*)d_in[3];
    const float* ro_bias  = (const float*)d_in[4];
    const float* eps      = (const float*)d_in[5];
    const float* eps_bias = (const float*)d_in[6];
    float* out = (float*)d_out;

    dim3 grid(ISPLITS, BTILES);
    main_kernel<<<grid, THREADS>>>(x, mu, ro, eps);

    reduce_kernel<<<(BATCH * DOUT / 4) / RED_OUTS, RED_GROUPS * RED_OUTS>>>(
        mu_bias, ro_bias, eps_bias, out);
}

// round 9
// speedup vs baseline: 1.3337x; 1.0054x over previous
#include <cuda_runtime.h>
#include <math.h>

#define BATCH    64
#define DIN      1024
#define DOUT     1024
#define ISPLITS  37                  // grid = 37*8 = 296 = 2 CTAs per SM (148 SMs)
#define CHUNK_HI 28                  // first 25 chunks: 28 rows
#define CHUNK_LO 27                  // last 12 chunks: 27 rows (25*28+12*27 = 1024)
#define N_HI     25
#define BTILE    8
#define BTILES   (BATCH / BTILE)     // 8
#define THREADS  256                 // 256 threads * float4 = 1024 = DOUT

// Scratch (static __device__ global — allocation-free per harness rules)
__device__ float g_part[ISPLITS * BATCH * DOUT];   // 9.7 MB: i-split partials
                                                   // (kept L2-resident: default
                                                   //  store policy, NOT evict-first)

// Fast softplus: max(v,0) + log1p(exp(-|v|)) with MUFU intrinsics.
__device__ __forceinline__ float softplus_fast(float v) {
    float e = __expf(-fabsf(v));
    return fmaxf(v, 0.0f) + __logf(1.0f + e);
}

// ---------------------------------------------------------------------------
// Kernel 1 (main): streaming batched matvec partials with inline softplus.
// grid = (ISPLITS, BTILES) = (37, 8) = 296 CTAs -> exactly 2 per SM, balanced.
// Each CTA: 8 batches x {27|28} i-rows x all 1024 o. Thread: 4 consecutive o.
// eps uses evict-first (touched once chip-wide); ro/mu default policy so they
// stay L2-resident across the 8 b-tiles; partials default policy so the
// reduce kernel hits them in L2 instead of DRAM.
// ---------------------------------------------------------------------------
__global__ __launch_bounds__(THREADS) void main_kernel(
    const float* __restrict__ x,
    const float* __restrict__ mu,
    const float* __restrict__ ro,
    const float* __restrict__ eps)
{
    const int ic  = blockIdx.x;          // i-chunk: 0..36
    const int bt  = blockIdx.y;          // b-tile:  0..7
    const int len = (ic < N_HI) ? CHUNK_HI : CHUNK_LO;
    const int i0  = (ic < N_HI) ? ic * CHUNK_HI
                                : N_HI * CHUNK_HI + (ic - N_HI) * CHUNK_LO;
    const int b0  = bt * BTILE;
    const int o4  = threadIdx.x;         // float4 index along o

    __shared__ float sx[BTILE][CHUNK_HI];   // 8 x 28 max
    {
        const int t = threadIdx.x;
        if (t < BTILE * len) {              // <= 224 < 256
            const int bb = t / len;
            const int ii = t % len;
            sx[bb][ii] = x[(b0 + bb) * DIN + i0 + ii];
        }
    }
    __syncthreads();

    float4 acc[BTILE];
#pragma unroll
    for (int bb = 0; bb < BTILE; bb++) acc[bb] = make_float4(0.f, 0.f, 0.f, 0.f);

    const float4* ro4  = reinterpret_cast<const float4*>(ro);
    const float4* mu4  = reinterpret_cast<const float4*>(mu);
    const float4* eps4 = reinterpret_cast<const float4*>(eps);

    int row   = i0 * (DOUT / 4) + o4;               // ro/mu float4 index
    int ebase = (b0 * DIN + i0) * (DOUT / 4) + o4;  // eps float4 index (<=16.7M)

#pragma unroll 4
    for (int ii = 0; ii < len; ii++) {
        const float4 r = ro4[row];
        const float4 m = mu4[row];
        float4 sg;
        sg.x = softplus_fast(r.x);
        sg.y = softplus_fast(r.y);
        sg.z = softplus_fast(r.z);
        sg.w = softplus_fast(r.w);
#pragma unroll
        for (int bb = 0; bb < BTILE; bb++) {
            const float  xv = sx[bb][ii];
            const float4 e  = __ldcs(&eps4[ebase + bb * (DIN * (DOUT / 4))]);
            acc[bb].x = fmaf(xv, fmaf(e.x, sg.x, m.x), acc[bb].x);
            acc[bb].y = fmaf(xv, fmaf(e.y, sg.y, m.y), acc[bb].y);
            acc[bb].z = fmaf(xv, fmaf(e.z, sg.z, m.z), acc[bb].z);
            acc[bb].w = fmaf(xv, fmaf(e.w, sg.w, m.w), acc[bb].w);
        }
        row   += DOUT / 4;
        ebase += DOUT / 4;
    }

    // DEFAULT store policy (evict-normal): keep partials in L2 for the reduce.
    float4* p4 = reinterpret_cast<float4*>(g_part);
#pragma unroll
    for (int bb = 0; bb < BTILE; bb++) {
        p4[(ic * BATCH + b0 + bb) * (DOUT / 4) + o4] = acc[bb];
    }
}

// ---------------------------------------------------------------------------
// Kernel 2: deterministic reduction over ISPLITS partials + bias.
// 512 blocks x 256 threads = 128K threads. Block = 8 split-groups x 32
// output-float4s. Each thread sums <=5 splits (L2 hits), 8-way smem reduce,
// then bias + store.
// ---------------------------------------------------------------------------
#define RED_GROUPS 8
#define RED_OUTS   32                // float4 outputs per block
#define SPG        5                 // ceil(37/8): groups 0..6 get 5, group 7 gets 2

__global__ __launch_bounds__(RED_GROUPS * RED_OUTS) void reduce_kernel(
    const float* __restrict__ mu_bias,
    const float* __restrict__ ro_bias,
    const float* __restrict__ eps_bias,
    float* __restrict__ out)
{
    const int t  = threadIdx.x & (RED_OUTS - 1);    // output lane within block
    const int g  = threadIdx.x / RED_OUTS;          // split group 0..7
    const int g4 = blockIdx.x * RED_OUTS + t;       // float4 idx over B*DOUT/4

    const float4* p4 = reinterpret_cast<const float4*>(g_part);

    const int s_lo = g * SPG;
    const int s_hi = min(ISPLITS, s_lo + SPG);
    float4 sum = make_float4(0.f, 0.f, 0.f, 0.f);
    for (int s = s_lo; s < s_hi; s++) {
        const float4 p = __ldcs(&p4[s * (BATCH * DOUT / 4) + g4]);
        sum.x += p.x; sum.y += p.y; sum.z += p.z; sum.w += p.w;
    }

    __shared__ float4 red[RED_GROUPS][RED_OUTS];
    red[g][t] = sum;
    __syncthreads();

    if (g == 0) {
#pragma unroll
        for (int k = 1; k < RED_GROUPS; k++) {
            const float4 p = red[k][t];
            sum.x += p.x; sum.y += p.y; sum.z += p.z; sum.w += p.w;
        }
        const int o4 = g4 & (DOUT / 4 - 1);
        const float4 rb = reinterpret_cast<const float4*>(ro_bias)[o4];
        const float4 mb = reinterpret_cast<const float4*>(mu_bias)[o4];
        const float4 eb = reinterpret_cast<const float4*>(eps_bias)[g4];

        float4 r;
        r.x = sum.x + fmaf(eb.x, softplus_fast(rb.x), mb.x);
        r.y = sum.y + fmaf(eb.y, softplus_fast(rb.y), mb.y);
        r.z = sum.z + fmaf(eb.z, softplus_fast(rb.z), mb.z);
        r.w = sum.w + fmaf(eb.w, softplus_fast(rb.w), mb.w);
        reinterpret_cast<float4*>(out)[g4] = r;
    }
}

// ---------------------------------------------------------------------------
// Launch. Inputs (metadata order): x, mu, ro, mu_bias, ro_bias, eps, eps_bias
// ---------------------------------------------------------------------------
extern "C" void kernel_launch(void* const* d_in, const int* in_sizes, int n_in,
                              void* d_out, int out_size) {
    const float* x        = (const float*)d_in[0];
    const float* mu       = (const float*)d_in[1];
    const float* ro       = (const float*)d_in[2];
    const float* mu_bias  = (const float*)d_in[3];
    const float* ro_bias  = (const float*)d_in[4];
    const float* eps      = (const float*)d_in[5];
    const float* eps_bias = (const float*)d_in[6];
    float* out = (float*)d_out;

    dim3 grid(ISPLITS, BTILES);
    main_kernel<<<grid, THREADS>>>(x, mu, ro, eps);

    reduce_kernel<<<(BATCH * DOUT / 4) / RED_OUTS, RED_GROUPS * RED_OUTS>>>(
        mu_bias, ro_bias, eps_bias, out);
}